// round 7
// baseline (speedup 1.0000x reference)
#include <cuda_runtime.h>
#include <cstdint>

// Fused feature replacement, forced-MLP + write-through stores.
//
// Layout: [B=32, C=512, HW=784] fp32 -> 196 float4 per (b,c) slice.
// Block tile = 2048 contiguous float4s (8 per thread, 256 threads).
// 3,211,264 / 2048 = 1568 blocks exactly -> no bounds guards needed.
// A tile spans <= 11 consecutive channels -> 16-entry shared mask built from
// the 256 replacement indices (one guarded load per thread).
//
// Memory policy:
//  - loads: default .ca -> inputs (103 MB) populate L2 (~120 MB usable) and
//    stay resident across graph replays.
//  - stores: .wt write-through -> output lines never ALLOCATE in L2, so they
//    cannot evict the resident inputs. Steady-state DRAM traffic ~= writes only.

__global__ void __launch_bounds__(256)
fused_replace_kernel(const float4* __restrict__ out_src,
                     const float4* __restrict__ feat_src,
                     float4* __restrict__ dst,
                     const int* __restrict__ idx,
                     int num_replace)
{
    __shared__ int smask[16];

    const int tid  = threadIdx.x;
    const int B0   = blockIdx.x << 11;       // first float4 index of this tile
    const int s_lo = B0 / 196;               // first (b,c) slice index
    const int c_base = s_lo & 511;           // its channel (C=512, pow2)

    if (tid < 16) smask[tid] = 0;
    __syncthreads();

    // Mark replaced channels falling inside this tile's <=11-channel window.
    if (tid < num_replace) {
        int r = idx[tid] - c_base;           // indices are int32 (JAX x64 off)
        if (r >= 0 && r < 16) smask[r] = 1;
    }
    for (int t = tid + 256; t < num_replace; t += 256) {   // general tail
        int r = idx[t] - c_base;
        if (r >= 0 && r < 16) smask[r] = 1;
    }
    __syncthreads();

    const int i0 = B0 + tid;

    // Phase 1: resolve the 8 source addresses.
    const float4* src[8];
#pragma unroll
    for (int k = 0; k < 8; k++) {
        int i   = i0 + (k << 8);
        int rel = i / 196 - s_lo;            // 0..10 within this tile
        src[k] = (smask[rel] ? feat_src : out_src) + i;
    }

    // Phase 2: eight independent 128-bit loads, issued back-to-back (MLP=8).
    float4 v[8];
#pragma unroll
    for (int k = 0; k < 8; k++) {
        asm volatile("ld.global.v4.f32 {%0,%1,%2,%3}, [%4];"
                     : "=f"(v[k].x), "=f"(v[k].y), "=f"(v[k].z), "=f"(v[k].w)
                     : "l"(src[k]));
    }

    // Phase 3: write-through stores (no L2 allocation for dead output lines).
#pragma unroll
    for (int k = 0; k < 8; k++) {
        __stwt(dst + i0 + (k << 8), v[k]);
    }
}

extern "C" void kernel_launch(void* const* d_in, const int* in_sizes, int n_in,
                              void* d_out, int out_size)
{
    const float* out_t  = (const float*)d_in[0];   // output             [32,512,28,28] f32
    const float* feat_t = (const float*)d_in[1];   // matryoshka_features[32,512,28,28] f32
    const int*   idx    = (const int*)d_in[2];     // indices (int32)    [256]

    const int num_replace = in_sizes[2];           // 256
    const int n4 = out_size / 4;                   // 3,211,264 float4s
    const int blocks = n4 >> 11;                   // 1568 (exact)

    fused_replace_kernel<<<blocks, 256>>>((const float4*)out_t,
                                          (const float4*)feat_t,
                                          (float4*)d_out,
                                          idx, num_replace);
}

// round 9
// speedup vs baseline: 1.2227x; 1.2227x over previous
#include <cuda_runtime.h>
#include <cstdint>

// Fused feature replacement — software-pipelined asm version.
//
// Layout: [B=32, C=512, HW=784] fp32 -> 196 float4 per (b,c) slice.
// Block tile = 2048 contiguous float4s (8 per thread, 256 threads);
// 3,211,264 / 2048 = 1568 blocks exactly (no guards). A tile spans <= 11
// consecutive channels -> 16-bit packed mask built with one smem atomicOr.
//
// Issue order is pinned by volatile asm:
//   L0 L1 L2 L3 | L4 S0 L5 S1 L6 S2 L7 S3 | S4 S5 S6 S7
// >=4 loads in flight at all times, load/store streams interleaved.
// Loads: ld.global.nc (read-only path). Stores: st.global.cs (evict-first:
// output lines don't churn the L2-resident inputs; proven best in R5 vs R7).

__global__ void __launch_bounds__(256, 6)
fused_replace_kernel(const float4* __restrict__ out_src,
                     const float4* __restrict__ feat_src,
                     float4* __restrict__ dst,
                     const int* __restrict__ idx,
                     int num_replace)
{
    __shared__ unsigned mword;

    const int tid   = threadIdx.x;
    const int B0    = blockIdx.x << 11;      // first float4 index of this tile
    const int s_lo  = B0 / 196;              // first (b,c) slice index
    const int c_base = s_lo & 511;           // its channel (C=512, pow2)

    if (tid == 0) mword = 0u;
    __syncthreads();

    if (tid < num_replace) {                 // indices are int32 (JAX x64 off)
        int r = idx[tid] - c_base;
        if (r >= 0 && r < 16) atomicOr(&mword, 1u << r);
    }
    for (int t = tid + 256; t < num_replace; t += 256) {   // general tail
        int r = idx[t] - c_base;
        if (r >= 0 && r < 16) atomicOr(&mword, 1u << r);
    }
    __syncthreads();

    const unsigned bmask = mword;            // broadcast LDS, then pure ALU
    const int i0 = B0 + tid;

    float4 v[8];

#define RELSEL(k, pvar)                                                        \
    const float4* pvar;                                                        \
    {                                                                          \
        int i   = i0 + ((k) << 8);                                             \
        int rel = i / 196 - s_lo;            /* 0..10 in this tile */          \
        pvar = (((bmask >> rel) & 1u) ? feat_src : out_src) + i;               \
    }

#define LOADK(k)                                                               \
    {                                                                          \
        RELSEL(k, p##k)                                                        \
        asm volatile("ld.global.nc.v4.f32 {%0,%1,%2,%3}, [%4];"                \
                     : "=f"(v[k].x), "=f"(v[k].y), "=f"(v[k].z), "=f"(v[k].w)  \
                     : "l"(p##k));                                             \
    }

#define STORK(k)                                                               \
    {                                                                          \
        const float4* q##k = dst + i0 + ((k) << 8);                            \
        asm volatile("st.global.cs.v4.f32 [%0], {%1,%2,%3,%4};"                \
                     :: "l"(q##k),                                             \
                        "f"(v[k].x), "f"(v[k].y), "f"(v[k].z), "f"(v[k].w)     \
                     : "memory");                                              \
    }

    // Prologue: fill the load window.
    LOADK(0) LOADK(1) LOADK(2) LOADK(3)
    // Steady state: one load ahead per store, window stays >= 4 deep.
    LOADK(4) STORK(0)
    LOADK(5) STORK(1)
    LOADK(6) STORK(2)
    LOADK(7) STORK(3)
    // Drain.
    STORK(4) STORK(5) STORK(6) STORK(7)

#undef RELSEL
#undef LOADK
#undef STORK
}

extern "C" void kernel_launch(void* const* d_in, const int* in_sizes, int n_in,
                              void* d_out, int out_size)
{
    const float* out_t  = (const float*)d_in[0];   // output             [32,512,28,28] f32
    const float* feat_t = (const float*)d_in[1];   // matryoshka_features[32,512,28,28] f32
    const int*   idx    = (const int*)d_in[2];     // indices (int32)    [256]

    const int num_replace = in_sizes[2];           // 256
    const int n4 = out_size / 4;                   // 3,211,264 float4s
    const int blocks = n4 >> 11;                   // 1568 (exact)

    fused_replace_kernel<<<blocks, 256>>>((const float4*)out_t,
                                          (const float4*)feat_t,
                                          (float4*)d_out,
                                          idx, num_replace);
}